// round 14
// baseline (speedup 1.0000x reference)
#include <cuda_runtime.h>

// Problem constants (fixed by the reference setup_inputs)
#define B_   8
#define N_   256
#define D_   16
#define KP1_ 4
#define REL_ 6
#define OUT_ 3
#define ROW_ (D_ * KP1_)   // 64 floats per (b, node)
#define TPB_ 1024

// Inputs (metadata order): As (ignored), Xs (B,N,D,K+1) f32, W (64,3) f32
// Output: actions (B, N, 3) f32
//
// A = J - I (reference overwrites As), N=256:
//   L = J - 256 I,  L^2 = 65536 I - 256 J,  A^2 = 254 J + I
//   T_k[b,d] = sum_j Xs[b,j,d,k]
//   Zagg[b,i,d,0] = rel ? 0                          : X0
//   Zagg[b,i,d,1] = rel ? T1 - 256 X1                : T1 - X1
//   Zagg[b,i,d,2] = rel ? 256 X2 - T2 - 255 X1       : 254 T2 + X2
//   Zagg[b,i,d,3] = rel ? 256 T3 - 65536 X3 - 255 X1 : 64771 T3 - X3
//   actions = Zagg @ W, NaN -> 0

__global__ __launch_bounds__(TPB_, 1) void reynolds_kernel(
    const float* __restrict__ Xs,   // (B, N, 64)
    const float* __restrict__ W,    // (64, 3)
    float* __restrict__ out)        // (B, N, 3)
{
    const int b    = blockIdx.x;
    const int tid  = threadIdx.x;         // 0..1023
    const int c4   = tid & 15;            // float4 channel group
    const int jg   = tid >> 4;            // row phase 0..63
    const int node = tid >> 2;            // 0..255  (phase-3 mapping)
    const int q    = tid & 3;             // quarter of row: d = q*4 .. q*4+3

    __shared__ float Sp[64][ROW_];        // partial column sums   (16 KB)
    __shared__ float T[ROW_];             // final column sums
    __shared__ float Ws[ROW_ * OUT_];     // 192 floats

    const float4* Xb = reinterpret_cast<const float4*>(Xs + (size_t)b * N_ * ROW_);

    // ---- Front-batched loads: 8 independent LDG.128 per thread ----
    // Column-sum sweep: rows jg + 64*s, channel group c4.
    float4 v[4];
#pragma unroll
    for (int s = 0; s < 4; s++)
        v[s] = Xb[(size_t)(jg + 64 * s) * (ROW_ / 4) + c4];

    // Quarter of this thread's node row (d = q*4 .. q*4+3).
    float4 x[4];
#pragma unroll
    for (int s = 0; s < 4; s++)
        x[s] = Xb[(size_t)node * (ROW_ / 4) + q * 4 + s];

    if (tid < ROW_ * OUT_) Ws[tid] = W[tid];

    // ---- Reduce 4 row samples, store partial ----
    float4 p;
    p.x = (v[0].x + v[1].x) + (v[2].x + v[3].x);
    p.y = (v[0].y + v[1].y) + (v[2].y + v[3].y);
    p.z = (v[0].z + v[1].z) + (v[2].z + v[3].z);
    p.w = (v[0].w + v[1].w) + (v[2].w + v[3].w);
    reinterpret_cast<float4*>(&Sp[jg][0])[c4] = p;
    __syncthreads();

    // ---- Fold 64 partials (thread -> column, conflict-free LDS) ----
    if (tid < ROW_) {
        float a0 = 0.f, a1 = 0.f, a2 = 0.f, a3 = 0.f;
#pragma unroll
        for (int pp = 0; pp < 64; pp += 4) {
            a0 += Sp[pp + 0][tid];
            a1 += Sp[pp + 1][tid];
            a2 += Sp[pp + 2][tid];
            a3 += Sp[pp + 3][tid];
        }
        T[tid] = (a0 + a1) + (a2 + a3);
    }
    __syncthreads();

    // ---- Phase 3: closed form + tiny GEMV over 4 channels per thread ----
    const float Nf  = 256.0f;
    const float N2f = 65536.0f;
    const float Nm1 = 255.0f;
    const float Nm2 = 254.0f;
    const float C3  = 64771.0f;            // N^2 - 3N + 3

    float acc0 = 0.f, acc1 = 0.f, acc2 = 0.f;

#pragma unroll
    for (int s = 0; s < 4; s++) {
        const int d = q * 4 + s;
        const float t1 = T[d * 4 + 1];
        const float t2 = T[d * 4 + 2];
        const float t3 = T[d * 4 + 3];
        const bool rel = (d < REL_);

        const float z0 = rel ? 0.0f : x[s].x;
        const float z1 = rel ? (t1 - Nf * x[s].y)
                             : (t1 - x[s].y);
        const float z2 = rel ? (Nf * x[s].z - t2 - Nm1 * x[s].y)
                             : (Nm2 * t2 + x[s].z);
        const float z3 = rel ? (Nf * t3 - N2f * x[s].w - Nm1 * x[s].y)
                             : (C3 * t3 - x[s].w);

        const float* w = &Ws[d * KP1_ * OUT_];
        acc0 += z0 * w[0] + z1 * w[3] + z2 * w[6] + z3 * w[9];
        acc1 += z0 * w[1] + z1 * w[4] + z2 * w[7] + z3 * w[10];
        acc2 += z0 * w[2] + z1 * w[5] + z2 * w[8] + z3 * w[11];
    }

    // Combine the 4 quarter-partials within each quad.
    acc0 += __shfl_down_sync(0xffffffffu, acc0, 2, 4);
    acc1 += __shfl_down_sync(0xffffffffu, acc1, 2, 4);
    acc2 += __shfl_down_sync(0xffffffffu, acc2, 2, 4);
    acc0 += __shfl_down_sync(0xffffffffu, acc0, 1, 4);
    acc1 += __shfl_down_sync(0xffffffffu, acc1, 1, 4);
    acc2 += __shfl_down_sync(0xffffffffu, acc2, 1, 4);

    if (q == 0) {
        // NaN guard (reference: where(isnan, 0))
        if (isnan(acc0)) acc0 = 0.0f;
        if (isnan(acc1)) acc1 = 0.0f;
        if (isnan(acc2)) acc2 = 0.0f;

        float* o = out + ((size_t)(b * N_) + node) * OUT_;
        o[0] = acc0;
        o[1] = acc1;
        o[2] = acc2;
    }
}

extern "C" void kernel_launch(void* const* d_in, const int* in_sizes, int n_in,
                              void* d_out, int out_size)
{
    // d_in[0] = As (ignored: reference overwrites it with J - I)
    const float* Xs = (const float*)d_in[1];
    const float* W  = (const float*)d_in[2];
    float* out      = (float*)d_out;

    reynolds_kernel<<<B_, TPB_>>>(Xs, W, out);
}

// round 15
// speedup vs baseline: 1.0368x; 1.0368x over previous
#include <cuda_runtime.h>

// Problem constants (fixed by the reference setup_inputs)
#define B_   8
#define N_   256
#define D_   16
#define KP1_ 4
#define REL_ 6
#define OUT_ 3
#define ROW_ (D_ * KP1_)   // 64 floats per (b, node)
#define TPB_ 1024

// Inputs (metadata order): As (ignored), Xs (B,N,D,K+1) f32, W (64,3) f32
// Output: actions (B, N, 3) f32
//
// A = J - I (reference overwrites As), N=256:
//   L = J - 256 I,  L^2 = 65536 I - 256 J,  A^2 = 254 J + I
//   T_k[b,d] = sum_j Xs[b,j,d,k]
//   Zagg[b,i,d,0] = rel ? 0                          : X0
//   Zagg[b,i,d,1] = rel ? T1 - 256 X1                : T1 - X1
//   Zagg[b,i,d,2] = rel ? 256 X2 - T2 - 255 X1       : 254 T2 + X2
//   Zagg[b,i,d,3] = rel ? 256 T3 - 65536 X3 - 255 X1 : 64771 T3 - X3
//   actions = Zagg @ W, NaN -> 0

__global__ __launch_bounds__(TPB_, 1) void reynolds_kernel(
    const float* __restrict__ Xs,   // (B, N, 64)
    const float* __restrict__ W,    // (64, 3)
    float* __restrict__ out)        // (B, N, 3)
{
    const int b    = blockIdx.x;
    const int tid  = threadIdx.x;         // 0..1023
    const int c4   = tid & 15;            // float4 channel group
    const int jg   = tid >> 4;            // row phase 0..63
    const int node = tid >> 2;            // 0..255  (phase-3 mapping)
    const int q    = tid & 3;             // quarter of row: d = q*4 .. q*4+3

    __shared__ float Sp[64][ROW_];        // partial column sums   (16 KB)
    __shared__ float T[ROW_];             // final column sums
    __shared__ float Ws[ROW_ * OUT_];     // 192 floats

    const float4* Xb = reinterpret_cast<const float4*>(Xs + (size_t)b * N_ * ROW_);

    // ---- Front-batched loads: 8 independent LDG.128 per thread ----
    // Column-sum sweep: rows jg + 64*s, channel group c4.
    float4 v[4];
#pragma unroll
    for (int s = 0; s < 4; s++)
        v[s] = Xb[(size_t)(jg + 64 * s) * (ROW_ / 4) + c4];

    // Quarter of this thread's node row (d = q*4 .. q*4+3).
    float4 x[4];
#pragma unroll
    for (int s = 0; s < 4; s++)
        x[s] = Xb[(size_t)node * (ROW_ / 4) + q * 4 + s];

    if (tid < ROW_ * OUT_) Ws[tid] = W[tid];

    // ---- Reduce 4 row samples, store partial ----
    float4 p;
    p.x = (v[0].x + v[1].x) + (v[2].x + v[3].x);
    p.y = (v[0].y + v[1].y) + (v[2].y + v[3].y);
    p.z = (v[0].z + v[1].z) + (v[2].z + v[3].z);
    p.w = (v[0].w + v[1].w) + (v[2].w + v[3].w);
    reinterpret_cast<float4*>(&Sp[jg][0])[c4] = p;
    __syncthreads();

    // ---- Fold 64 partials (thread -> column, conflict-free LDS) ----
    if (tid < ROW_) {
        float a0 = 0.f, a1 = 0.f, a2 = 0.f, a3 = 0.f;
#pragma unroll
        for (int pp = 0; pp < 64; pp += 4) {
            a0 += Sp[pp + 0][tid];
            a1 += Sp[pp + 1][tid];
            a2 += Sp[pp + 2][tid];
            a3 += Sp[pp + 3][tid];
        }
        T[tid] = (a0 + a1) + (a2 + a3);
    }
    __syncthreads();

    // ---- Phase 3: closed form + tiny GEMV over 4 channels per thread ----
    const float Nf  = 256.0f;
    const float N2f = 65536.0f;
    const float Nm1 = 255.0f;
    const float Nm2 = 254.0f;
    const float C3  = 64771.0f;            // N^2 - 3N + 3

    float acc0 = 0.f, acc1 = 0.f, acc2 = 0.f;

#pragma unroll
    for (int s = 0; s < 4; s++) {
        const int d = q * 4 + s;
        const float t1 = T[d * 4 + 1];
        const float t2 = T[d * 4 + 2];
        const float t3 = T[d * 4 + 3];
        const bool rel = (d < REL_);

        const float z0 = rel ? 0.0f : x[s].x;
        const float z1 = rel ? (t1 - Nf * x[s].y)
                             : (t1 - x[s].y);
        const float z2 = rel ? (Nf * x[s].z - t2 - Nm1 * x[s].y)
                             : (Nm2 * t2 + x[s].z);
        const float z3 = rel ? (Nf * t3 - N2f * x[s].w - Nm1 * x[s].y)
                             : (C3 * t3 - x[s].w);

        const float* w = &Ws[d * KP1_ * OUT_];
        acc0 += z0 * w[0] + z1 * w[3] + z2 * w[6] + z3 * w[9];
        acc1 += z0 * w[1] + z1 * w[4] + z2 * w[7] + z3 * w[10];
        acc2 += z0 * w[2] + z1 * w[5] + z2 * w[8] + z3 * w[11];
    }

    // Combine the 4 quarter-partials within each quad.
    acc0 += __shfl_down_sync(0xffffffffu, acc0, 2, 4);
    acc1 += __shfl_down_sync(0xffffffffu, acc1, 2, 4);
    acc2 += __shfl_down_sync(0xffffffffu, acc2, 2, 4);
    acc0 += __shfl_down_sync(0xffffffffu, acc0, 1, 4);
    acc1 += __shfl_down_sync(0xffffffffu, acc1, 1, 4);
    acc2 += __shfl_down_sync(0xffffffffu, acc2, 1, 4);

    if (q == 0) {
        // NaN guard (reference: where(isnan, 0))
        if (isnan(acc0)) acc0 = 0.0f;
        if (isnan(acc1)) acc1 = 0.0f;
        if (isnan(acc2)) acc2 = 0.0f;

        float* o = out + ((size_t)(b * N_) + node) * OUT_;
        o[0] = acc0;
        o[1] = acc1;
        o[2] = acc2;
    }
}

extern "C" void kernel_launch(void* const* d_in, const int* in_sizes, int n_in,
                              void* d_out, int out_size)
{
    // d_in[0] = As (ignored: reference overwrites it with J - I)
    const float* Xs = (const float*)d_in[1];
    const float* W  = (const float*)d_in[2];
    float* out      = (float*)d_out;

    reynolds_kernel<<<B_, TPB_>>>(Xs, W, out);
}

// round 16
// speedup vs baseline: 1.2936x; 1.2477x over previous
#include <cuda_runtime.h>

// Problem constants (fixed by the reference setup_inputs)
#define B_   8
#define N_   256
#define D_   16
#define KP1_ 4
#define REL_ 6
#define OUT_ 3
#define ROW_ (D_ * KP1_)   // 64 floats per (b, node)
#define TPB_ 1024

// Inputs (metadata order): As (ignored), Xs (B,N,D,K+1) f32, W (64,3) f32
// Output: actions (B, N, 3) f32
//
// A = J - I (reference overwrites As), N=256:
//   L = J - 256 I,  L^2 = 65536 I - 256 J,  A^2 = 254 J + I
//   T_k[b,d] = sum_j Xs[b,j,d,k]
//   Zagg[b,i,d,0] = rel ? 0                          : X0
//   Zagg[b,i,d,1] = rel ? T1 - 256 X1                : T1 - X1
//   Zagg[b,i,d,2] = rel ? 256 X2 - T2 - 255 X1       : 254 T2 + X2
//   Zagg[b,i,d,3] = rel ? 256 T3 - 65536 X3 - 255 X1 : 64771 T3 - X3
//   actions = Zagg @ W, NaN -> 0
//
// Key layout trick: thread (jg = tid>>4, c4 = tid&15) loads v[s] =
// Xs[b, jg+64s, d=c4, 0..3] as one float4. Those SAME registers serve both
// the column-sum reduction (phase 1) and the per-node closed form (phase 3,
// reduced across c4 with width-16 shuffles). The batch is read from global
// exactly once.

__global__ __launch_bounds__(TPB_, 1) void reynolds_kernel(
    const float* __restrict__ Xs,   // (B, N, 64)
    const float* __restrict__ W,    // (64, 3)
    float* __restrict__ out)        // (B, N, 3)
{
    const int b    = blockIdx.x;
    const int tid  = threadIdx.x;         // 0..1023
    const int c4   = tid & 15;            // d index (channel group)
    const int jg   = tid >> 4;            // row phase 0..63
    const int warp = tid >> 5;            // 0..31
    const int lane = tid & 31;

    __shared__ float Sp[32][ROW_];        // per-warp partial column sums (8 KB)
    __shared__ float T[ROW_];             // final column sums
    __shared__ float Ws[ROW_ * OUT_];     // 192 floats

    const float4* Xb = reinterpret_cast<const float4*>(Xs + (size_t)b * N_ * ROW_);

    // ---- Single load phase: 4 independent LDG.128 (rows jg+64s, d = c4) ----
    float4 v[4];
#pragma unroll
    for (int s = 0; s < 4; s++)
        v[s] = Xb[(size_t)(jg + 64 * s) * (ROW_ / 4) + c4];

    if (tid < ROW_ * OUT_) Ws[tid] = W[tid];

    // ---- Column-sum partial: sum my 4 rows, then fold the warp's two jg ----
    float4 p;
    p.x = (v[0].x + v[1].x) + (v[2].x + v[3].x);
    p.y = (v[0].y + v[1].y) + (v[2].y + v[3].y);
    p.z = (v[0].z + v[1].z) + (v[2].z + v[3].z);
    p.w = (v[0].w + v[1].w) + (v[2].w + v[3].w);
    p.x += __shfl_xor_sync(0xffffffffu, p.x, 16);
    p.y += __shfl_xor_sync(0xffffffffu, p.y, 16);
    p.z += __shfl_xor_sync(0xffffffffu, p.z, 16);
    p.w += __shfl_xor_sync(0xffffffffu, p.w, 16);
    if (lane < 16)
        reinterpret_cast<float4*>(&Sp[warp][0])[c4] = p;
    __syncthreads();

    // ---- Fold 32 partials (thread -> channel, conflict-free LDS) ----
    if (tid < ROW_) {
        float a0 = 0.f, a1 = 0.f, a2 = 0.f, a3 = 0.f;
#pragma unroll
        for (int pp = 0; pp < 32; pp += 4) {
            a0 += Sp[pp + 0][tid];
            a1 += Sp[pp + 1][tid];
            a2 += Sp[pp + 2][tid];
            a3 += Sp[pp + 3][tid];
        }
        T[tid] = (a0 + a1) + (a2 + a3);
    }
    __syncthreads();

    // ---- Phase 3: closed form straight from v[] registers ----
    const float Nf  = 256.0f;
    const float N2f = 65536.0f;
    const float Nm1 = 255.0f;
    const float Nm2 = 254.0f;
    const float C3  = 64771.0f;            // N^2 - 3N + 3

    const float t1 = T[4 * c4 + 1];
    const float t2 = T[4 * c4 + 2];
    const float t3 = T[4 * c4 + 3];
    const bool rel = (c4 < REL_);

    // Weight rows for d = c4: 12 floats = 3 x LDS.128 (48B-aligned).
    const float4* wv = reinterpret_cast<const float4*>(Ws + 12 * c4);
    const float4 w0 = wv[0], w1 = wv[1], w2 = wv[2];

#pragma unroll
    for (int s = 0; s < 4; s++) {
        const float z0 = rel ? 0.0f : v[s].x;
        const float z1 = rel ? (t1 - Nf * v[s].y)
                             : (t1 - v[s].y);
        const float z2 = rel ? (Nf * v[s].z - t2 - Nm1 * v[s].y)
                             : (Nm2 * t2 + v[s].z);
        const float z3 = rel ? (Nf * t3 - N2f * v[s].w - Nm1 * v[s].y)
                             : (C3 * t3 - v[s].w);

        // acc_j = z0*W[12d+j] + z1*W[12d+3+j] + z2*W[12d+6+j] + z3*W[12d+9+j]
        float acc0 = z0 * w0.x + z1 * w0.w + z2 * w1.z + z3 * w2.y;
        float acc1 = z0 * w0.y + z1 * w1.x + z2 * w1.w + z3 * w2.z;
        float acc2 = z0 * w0.z + z1 * w1.y + z2 * w2.x + z3 * w2.w;

        // Reduce over the 16 channel lanes (width-16 segments keep the two
        // jg halves of the warp independent).
        acc0 += __shfl_down_sync(0xffffffffu, acc0, 8, 16);
        acc1 += __shfl_down_sync(0xffffffffu, acc1, 8, 16);
        acc2 += __shfl_down_sync(0xffffffffu, acc2, 8, 16);
        acc0 += __shfl_down_sync(0xffffffffu, acc0, 4, 16);
        acc1 += __shfl_down_sync(0xffffffffu, acc1, 4, 16);
        acc2 += __shfl_down_sync(0xffffffffu, acc2, 4, 16);
        acc0 += __shfl_down_sync(0xffffffffu, acc0, 2, 16);
        acc1 += __shfl_down_sync(0xffffffffu, acc1, 2, 16);
        acc2 += __shfl_down_sync(0xffffffffu, acc2, 2, 16);
        acc0 += __shfl_down_sync(0xffffffffu, acc0, 1, 16);
        acc1 += __shfl_down_sync(0xffffffffu, acc1, 1, 16);
        acc2 += __shfl_down_sync(0xffffffffu, acc2, 1, 16);

        if (c4 == 0) {
            // NaN guard (reference: where(isnan, 0))
            if (isnan(acc0)) acc0 = 0.0f;
            if (isnan(acc1)) acc1 = 0.0f;
            if (isnan(acc2)) acc2 = 0.0f;

            const int node = jg + 64 * s;
            float* o = out + ((size_t)(b * N_) + node) * OUT_;
            o[0] = acc0;
            o[1] = acc1;
            o[2] = acc2;
        }
    }
}

extern "C" void kernel_launch(void* const* d_in, const int* in_sizes, int n_in,
                              void* d_out, int out_size)
{
    // d_in[0] = As (ignored: reference overwrites it with J - I)
    const float* Xs = (const float*)d_in[1];
    const float* W  = (const float*)d_in[2];
    float* out      = (float*)d_out;

    reynolds_kernel<<<B_, TPB_>>>(Xs, W, out);
}

// round 17
// speedup vs baseline: 1.3558x; 1.0481x over previous
#include <cuda_runtime.h>

// Problem constants (fixed by the reference setup_inputs)
#define B_   8
#define N_   256
#define D_   16
#define KP1_ 4
#define REL_ 6
#define OUT_ 3
#define ROW_ (D_ * KP1_)   // 64 floats per (b, node)
#define TPB_ 1024

// Inputs (metadata order): As (ignored), Xs (B,N,D,K+1) f32, W (64,3) f32
// Output: actions (B, N, 3) f32
//
// A = J - I (reference overwrites As), N=256:
//   L = J - 256 I,  L^2 = 65536 I - 256 J,  A^2 = 254 J + I
//   T_k[b,d] = sum_j Xs[b,j,d,k]
//   Zagg[b,i,d,0] = rel ? 0                          : X0
//   Zagg[b,i,d,1] = rel ? T1 - 256 X1                : T1 - X1
//   Zagg[b,i,d,2] = rel ? 256 X2 - T2 - 255 X1       : 254 T2 + X2
//   Zagg[b,i,d,3] = rel ? 256 T3 - 65536 X3 - 255 X1 : 64771 T3 - X3
//   actions = Zagg @ W, NaN -> 0
//
// Key layout trick: thread (jg = tid>>4, c4 = tid&15) loads v[s] =
// Xs[b, jg+64s, d=c4, 0..3] as one float4. Those SAME registers serve both
// the column-sum reduction (phase 1) and the per-node closed form (phase 3,
// reduced across c4 with width-16 shuffles). The batch is read from global
// exactly once.

__global__ __launch_bounds__(TPB_, 1) void reynolds_kernel(
    const float* __restrict__ Xs,   // (B, N, 64)
    const float* __restrict__ W,    // (64, 3)
    float* __restrict__ out)        // (B, N, 3)
{
    const int b    = blockIdx.x;
    const int tid  = threadIdx.x;         // 0..1023
    const int c4   = tid & 15;            // d index (channel group)
    const int jg   = tid >> 4;            // row phase 0..63
    const int warp = tid >> 5;            // 0..31
    const int lane = tid & 31;

    __shared__ float Sp[32][ROW_];        // per-warp partial column sums (8 KB)
    __shared__ float T[ROW_];             // final column sums
    __shared__ float Ws[ROW_ * OUT_];     // 192 floats

    const float4* Xb = reinterpret_cast<const float4*>(Xs + (size_t)b * N_ * ROW_);

    // ---- Single load phase: 4 independent LDG.128 (rows jg+64s, d = c4) ----
    float4 v[4];
#pragma unroll
    for (int s = 0; s < 4; s++)
        v[s] = Xb[(size_t)(jg + 64 * s) * (ROW_ / 4) + c4];

    if (tid < ROW_ * OUT_) Ws[tid] = W[tid];

    // ---- Column-sum partial: sum my 4 rows, then fold the warp's two jg ----
    float4 p;
    p.x = (v[0].x + v[1].x) + (v[2].x + v[3].x);
    p.y = (v[0].y + v[1].y) + (v[2].y + v[3].y);
    p.z = (v[0].z + v[1].z) + (v[2].z + v[3].z);
    p.w = (v[0].w + v[1].w) + (v[2].w + v[3].w);
    p.x += __shfl_xor_sync(0xffffffffu, p.x, 16);
    p.y += __shfl_xor_sync(0xffffffffu, p.y, 16);
    p.z += __shfl_xor_sync(0xffffffffu, p.z, 16);
    p.w += __shfl_xor_sync(0xffffffffu, p.w, 16);
    if (lane < 16)
        reinterpret_cast<float4*>(&Sp[warp][0])[c4] = p;
    __syncthreads();

    // ---- Fold 32 partials (thread -> channel, conflict-free LDS) ----
    if (tid < ROW_) {
        float a0 = 0.f, a1 = 0.f, a2 = 0.f, a3 = 0.f;
#pragma unroll
        for (int pp = 0; pp < 32; pp += 4) {
            a0 += Sp[pp + 0][tid];
            a1 += Sp[pp + 1][tid];
            a2 += Sp[pp + 2][tid];
            a3 += Sp[pp + 3][tid];
        }
        T[tid] = (a0 + a1) + (a2 + a3);
    }
    __syncthreads();

    // ---- Phase 3: closed form straight from v[] registers ----
    const float Nf  = 256.0f;
    const float N2f = 65536.0f;
    const float Nm1 = 255.0f;
    const float Nm2 = 254.0f;
    const float C3  = 64771.0f;            // N^2 - 3N + 3

    const float t1 = T[4 * c4 + 1];
    const float t2 = T[4 * c4 + 2];
    const float t3 = T[4 * c4 + 3];
    const bool rel = (c4 < REL_);

    // Weight rows for d = c4: 12 floats = 3 x LDS.128 (48B-aligned).
    const float4* wv = reinterpret_cast<const float4*>(Ws + 12 * c4);
    const float4 w0 = wv[0], w1 = wv[1], w2 = wv[2];

#pragma unroll
    for (int s = 0; s < 4; s++) {
        const float z0 = rel ? 0.0f : v[s].x;
        const float z1 = rel ? (t1 - Nf * v[s].y)
                             : (t1 - v[s].y);
        const float z2 = rel ? (Nf * v[s].z - t2 - Nm1 * v[s].y)
                             : (Nm2 * t2 + v[s].z);
        const float z3 = rel ? (Nf * t3 - N2f * v[s].w - Nm1 * v[s].y)
                             : (C3 * t3 - v[s].w);

        // acc_j = z0*W[12d+j] + z1*W[12d+3+j] + z2*W[12d+6+j] + z3*W[12d+9+j]
        float acc0 = z0 * w0.x + z1 * w0.w + z2 * w1.z + z3 * w2.y;
        float acc1 = z0 * w0.y + z1 * w1.x + z2 * w1.w + z3 * w2.z;
        float acc2 = z0 * w0.z + z1 * w1.y + z2 * w2.x + z3 * w2.w;

        // Reduce over the 16 channel lanes (width-16 segments keep the two
        // jg halves of the warp independent).
        acc0 += __shfl_down_sync(0xffffffffu, acc0, 8, 16);
        acc1 += __shfl_down_sync(0xffffffffu, acc1, 8, 16);
        acc2 += __shfl_down_sync(0xffffffffu, acc2, 8, 16);
        acc0 += __shfl_down_sync(0xffffffffu, acc0, 4, 16);
        acc1 += __shfl_down_sync(0xffffffffu, acc1, 4, 16);
        acc2 += __shfl_down_sync(0xffffffffu, acc2, 4, 16);
        acc0 += __shfl_down_sync(0xffffffffu, acc0, 2, 16);
        acc1 += __shfl_down_sync(0xffffffffu, acc1, 2, 16);
        acc2 += __shfl_down_sync(0xffffffffu, acc2, 2, 16);
        acc0 += __shfl_down_sync(0xffffffffu, acc0, 1, 16);
        acc1 += __shfl_down_sync(0xffffffffu, acc1, 1, 16);
        acc2 += __shfl_down_sync(0xffffffffu, acc2, 1, 16);

        if (c4 == 0) {
            // NaN guard (reference: where(isnan, 0))
            if (isnan(acc0)) acc0 = 0.0f;
            if (isnan(acc1)) acc1 = 0.0f;
            if (isnan(acc2)) acc2 = 0.0f;

            const int node = jg + 64 * s;
            float* o = out + ((size_t)(b * N_) + node) * OUT_;
            o[0] = acc0;
            o[1] = acc1;
            o[2] = acc2;
        }
    }
}

extern "C" void kernel_launch(void* const* d_in, const int* in_sizes, int n_in,
                              void* d_out, int out_size)
{
    // d_in[0] = As (ignored: reference overwrites it with J - I)
    const float* Xs = (const float*)d_in[1];
    const float* W  = (const float*)d_in[2];
    float* out      = (float*)d_out;

    reynolds_kernel<<<B_, TPB_>>>(Xs, W, out);
}